// round 1
// baseline (speedup 1.0000x reference)
#include <cuda_runtime.h>
#include <cuda_bf16.h>
#include <math.h>

#define BATCH   4
#define L_SEQ   1024
#define DM      768
#define DI      1536
#define DS      16
#define DR      48
#define DEPTH   4

// ---------------- scratch (static device globals; no allocation) ----------------
__device__ float g_h  [BATCH*L_SEQ*DM];
__device__ float g_ho [BATCH*L_SEQ*DM];
__device__ float g_u  [BATCH*L_SEQ*DM];
__device__ float g_xz [BATCH*L_SEQ*2*DI];
__device__ float g_xs [BATCH*L_SEQ*DI];
__device__ float g_dbl[BATCH*L_SEQ*80];
__device__ float g_dt [BATCH*L_SEQ*DI];
__device__ float g_y  [BATCH*L_SEQ*DI];
__device__ float g_mid[BATCH*DM];
__device__ float g_c  [BATCH*DM];
__device__ float g_ada[BATCH*2*DM];
__device__ float g_A  [DEPTH*DI*DS];
__device__ int   g_pflag[DEPTH];

// ---------------- small helpers ----------------
__device__ __forceinline__ float silu_f(float v) { return v / (1.f + __expf(-v)); }

// ---------------- A precompute + pow-trick flag ----------------
__global__ void init_flags_kernel() {
    if (threadIdx.x < DEPTH) g_pflag[threadIdx.x] = 1;
}

__global__ void precompute_A_kernel(const float* __restrict__ A_log) {
    int idx = blockIdx.x * blockDim.x + threadIdx.x;
    if (idx >= DEPTH*DI*DS) return;
    int s = idx % DS;
    int layer = idx / (DI*DS);
    float a = -expf(A_log[idx]);
    g_A[idx] = a;
    float target = -(float)(s + 1);
    if (fabsf(a - target) > 2e-6f * (float)(s + 1))
        atomicAnd(&g_pflag[layer], 0);
}

// ---------------- patch embed: h = tok @ patch_w^T + patch_b + pos ----------------
__global__ void patch_kernel(const float* __restrict__ x,
                             const float* __restrict__ pw,
                             const float* __restrict__ pb,
                             const float* __restrict__ pos) {
    int idx = blockIdx.x * blockDim.x + threadIdx.x;
    if (idx >= BATCH*L_SEQ*DM) return;
    int m  = idx % DM;
    int bl = idx / DM;
    int b  = bl >> 10;
    int l  = bl & 1023;
    float acc = pb[m] + pos[(size_t)l*DM + m];
#pragma unroll
    for (int c = 0; c < 4; c++)
        acc = fmaf(x[((b*4 + c) << 10) + l], pw[m*4 + c], acc);
    g_h[idx] = acc;
}

// ---------------- time MLP ----------------
__global__ void tmlp1_kernel(const float* __restrict__ t,
                             const float* __restrict__ w1,
                             const float* __restrict__ b1) {
    int b = blockIdx.x;
    int tid = threadIdx.x;
    __shared__ float temb[256];
    {
        float tv = t[b];
        int f = tid;
        if (f < 128) {
            float fr = expf(-logf(10000.f) * (float)f / 128.f);
            temb[f] = cosf(tv * fr);
        } else {
            float fr = expf(-logf(10000.f) * (float)(f-128) / 128.f);
            temb[f] = sinf(tv * fr);
        }
    }
    __syncthreads();
    for (int m = tid; m < DM; m += 256) {
        float acc = b1[m];
        const float* w = w1 + (size_t)m * 256;
        for (int f = 0; f < 256; f++) acc = fmaf(temb[f], w[f], acc);
        g_mid[b*DM + m] = acc / (1.f + expf(-acc));
    }
}

__global__ void tmlp2_kernel(const float* __restrict__ w2,
                             const float* __restrict__ b2) {
    int b = blockIdx.x;
    int tid = threadIdx.x;
    for (int m = tid; m < DM; m += 256) {
        float acc = b2[m];
        const float* w = w2 + (size_t)m * DM;
        const float* mid = g_mid + b*DM;
        for (int k = 0; k < DM; k++) acc = fmaf(mid[k], w[k], acc);
        g_c[b*DM + m] = acc;
    }
}

__global__ void ada_kernel(const float* __restrict__ w,
                           const float* __restrict__ bias) {
    int b = blockIdx.x;
    int tid = threadIdx.x;
    __shared__ float sc[DM];
    for (int k = tid; k < DM; k += 256) {
        float cv = g_c[b*DM + k];
        sc[k] = cv / (1.f + expf(-cv));
    }
    __syncthreads();
    for (int n = tid; n < 2*DM; n += 256) {
        float acc = bias[n];
        const float* wr = w + (size_t)n * DM;
        for (int k = 0; k < DM; k++) acc = fmaf(sc[k], wr[k], acc);
        g_ada[b*2*DM + n] = acc;
    }
}

// ---------------- gather + LayerNorm ----------------
__global__ void ln_gather_kernel(const float* __restrict__ norm_w,
                                 const float* __restrict__ norm_b,
                                 const int* __restrict__ order,
                                 int layer) {
    int row = blockIdx.x;          // b*L + p
    int p = row & 1023;
    int b = row >> 10;
    int src = order[p];
    const float* hrow = g_h  + (size_t)(b*L_SEQ + src) * DM;
    float* horow      = g_ho + (size_t)row * DM;
    float* urow       = g_u  + (size_t)row * DM;
    int tid = threadIdx.x;

    float v[3];
    float s = 0.f, ss = 0.f;
#pragma unroll
    for (int j = 0; j < 3; j++) {
        v[j] = hrow[tid + j*256];
        s += v[j];
        ss = fmaf(v[j], v[j], ss);
    }
    __shared__ float sh[2][8];
    for (int o = 16; o > 0; o >>= 1) {
        s  += __shfl_xor_sync(0xffffffffu, s,  o);
        ss += __shfl_xor_sync(0xffffffffu, ss, o);
    }
    if ((tid & 31) == 0) { sh[0][tid >> 5] = s; sh[1][tid >> 5] = ss; }
    __syncthreads();
    if (tid < 32) {
        float a = (tid < 8) ? sh[0][tid] : 0.f;
        float c = (tid < 8) ? sh[1][tid] : 0.f;
        for (int o = 4; o > 0; o >>= 1) {
            a += __shfl_xor_sync(0xffffffffu, a, o);
            c += __shfl_xor_sync(0xffffffffu, c, o);
        }
        if (tid == 0) { sh[0][0] = a; sh[1][0] = c; }
    }
    __syncthreads();
    float mean = sh[0][0] * (1.f / DM);
    float var  = sh[1][0] * (1.f / DM) - mean * mean;
    float rs = rsqrtf(var + 1e-5f);
#pragma unroll
    for (int j = 0; j < 3; j++) {
        int m = tid + j*256;
        horow[m] = v[j];
        urow[m] = (v[j] - mean) * rs * norm_w[layer*DM + m] + norm_b[layer*DM + m];
    }
}

// ---------------- generic GEMM: C = act(A @ W^T + bias) (+add) with optional row scatter ----------------
// A: (M,K) row-major with lda, W: (N,K) row-major with ldw.
// act: 0 none, 2 softplus. add: optional residual read at row m. scat: optional
// row permutation for the store (out_row = (m/1024)*1024 + scat[m%1024]).
#define GBM 64
#define GBN 64
#define GBK 16

__global__ void __launch_bounds__(256)
gemm_tn_kernel(const float* __restrict__ A, int lda,
               const float* __restrict__ W, int ldw,
               float* __restrict__ C, int ldc,
               int M, int N, int K,
               const float* __restrict__ bias, int act,
               const float* __restrict__ add,
               const int* __restrict__ scat) {
    __shared__ float As[GBM][GBK + 1];
    __shared__ float Ws[GBN][GBK + 1];
    int tid = threadIdx.x;
    int m0 = blockIdx.y * GBM;
    int n0 = blockIdx.x * GBN;
    int tx = tid & 15;
    int ty = tid >> 4;
    float acc[4][4] = {};

    for (int kt = 0; kt < K; kt += GBK) {
#pragma unroll
        for (int i = 0; i < 4; i++) {
            int idx = tid + i*256;
            int m = idx >> 4, k = idx & 15;
            int gm = m0 + m, gk = kt + k;
            As[m][k] = (gm < M && gk < K) ? A[(size_t)gm*lda + gk] : 0.f;
        }
#pragma unroll
        for (int i = 0; i < 4; i++) {
            int idx = tid + i*256;
            int n = idx >> 4, k = idx & 15;
            int gn = n0 + n, gk = kt + k;
            Ws[n][k] = (gn < N && gk < K) ? W[(size_t)gn*ldw + gk] : 0.f;
        }
        __syncthreads();
#pragma unroll
        for (int k = 0; k < GBK; k++) {
            float a[4], w[4];
#pragma unroll
            for (int j = 0; j < 4; j++) a[j] = As[ty*4 + j][k];
#pragma unroll
            for (int j = 0; j < 4; j++) w[j] = Ws[tx*4 + j][k];
#pragma unroll
            for (int r = 0; r < 4; r++)
#pragma unroll
                for (int c = 0; c < 4; c++)
                    acc[r][c] = fmaf(a[r], w[c], acc[r][c]);
        }
        __syncthreads();
    }

#pragma unroll
    for (int r = 0; r < 4; r++) {
        int gm = m0 + ty*4 + r;
        if (gm >= M) continue;
        int orow = gm;
        if (scat) {
            int bb = gm >> 10;
            int p  = gm & 1023;
            orow = (bb << 10) + scat[p];
        }
#pragma unroll
        for (int c = 0; c < 4; c++) {
            int gn = n0 + tx*4 + c;
            if (gn >= N) continue;
            float v = acc[r][c];
            if (bias) v += bias[gn];
            if (act == 2) v = fmaxf(v, 0.f) + log1pf(__expf(-fabsf(v)));  // softplus
            if (add)  v += add[(size_t)gm*ldc + gn];
            C[(size_t)orow*ldc + gn] = v;
        }
    }
}

// ---------------- causal depthwise conv (k=4) + SiLU ----------------
__global__ void conv_silu_kernel(const float* __restrict__ conv_w,
                                 const float* __restrict__ conv_b,
                                 int layer) {
    int idx = blockIdx.x * blockDim.x + threadIdx.x;
    if (idx >= BATCH*L_SEQ*DI) return;
    int d   = idx % DI;
    int row = idx / DI;
    int p   = row & 1023;
    float acc = conv_b[layer*DI + d];
    const float* w = conv_w + ((size_t)(layer*DI + d)) * 4;
#pragma unroll
    for (int k = 0; k < 4; k++) {
        int pp = p - 3 + k;
        if (pp >= 0)
            acc = fmaf(w[k], g_xz[((size_t)(row - 3 + k)) * (2*DI) + d], acc);
    }
    g_xs[(size_t)row*DI + d] = silu_f(acc);
}

// ---------------- selective scan: one thread per (b,d) ----------------
__global__ void scan_kernel(int layer) {
    int t = blockIdx.x * blockDim.x + threadIdx.x;
    if (t >= BATCH*DI) return;
    int b = t / DI;
    int d = t % DI;
    int flag = g_pflag[layer];
    const float* arow = g_A + (size_t)(layer*DI + d) * DS;

    float hh[16];
#pragma unroll
    for (int s = 0; s < 16; s++) hh[s] = 0.f;

    size_t base = (size_t)b * L_SEQ;
    for (int p = 0; p < L_SEQ; p++) {
        size_t row = base + p;
        float dtv = g_dt[row*DI + d];
        float xv  = g_xs[row*DI + d];
        float dtx = dtv * xv;

        const float4* Bp = (const float4*)(g_dbl + row*80 + 48);
        const float4* Cp = (const float4*)(g_dbl + row*80 + 64);
        float Bv[16], Cv[16];
#pragma unroll
        for (int q = 0; q < 4; q++) {
            float4 fb = Bp[q];
            Bv[4*q+0] = fb.x; Bv[4*q+1] = fb.y; Bv[4*q+2] = fb.z; Bv[4*q+3] = fb.w;
            float4 fc = Cp[q];
            Cv[4*q+0] = fc.x; Cv[4*q+1] = fc.y; Cv[4*q+2] = fc.z; Cv[4*q+3] = fc.w;
        }

        float tm[16];
        if (flag) {
            // A[:,s] == -(s+1): exp(dt*A_s) = exp(-dt)^(s+1) via squaring
            float e1 = __expf(-dtv);
            float e2 = e1*e1, e4 = e2*e2, e8 = e4*e4;
            tm[0]=e1;      tm[1]=e2;      tm[2]=e2*e1;    tm[3]=e4;
            tm[4]=e4*e1;   tm[5]=e4*e2;   tm[6]=e4*tm[2]; tm[7]=e8;
            tm[8]=e8*e1;   tm[9]=e8*e2;   tm[10]=e8*tm[2];tm[11]=e8*e4;
            tm[12]=e8*tm[4];tm[13]=e8*tm[5];tm[14]=e8*tm[6];tm[15]=e8*e8;
        } else {
#pragma unroll
            for (int s = 0; s < 16; s++) tm[s] = __expf(dtv * arow[s]);
        }

        float a0=0.f, a1=0.f, a2=0.f, a3=0.f;
#pragma unroll
        for (int s = 0; s < 16; s += 4) {
            hh[s+0] = fmaf(hh[s+0], tm[s+0], dtx * Bv[s+0]); a0 = fmaf(hh[s+0], Cv[s+0], a0);
            hh[s+1] = fmaf(hh[s+1], tm[s+1], dtx * Bv[s+1]); a1 = fmaf(hh[s+1], Cv[s+1], a1);
            hh[s+2] = fmaf(hh[s+2], tm[s+2], dtx * Bv[s+2]); a2 = fmaf(hh[s+2], Cv[s+2], a2);
            hh[s+3] = fmaf(hh[s+3], tm[s+3], dtx * Bv[s+3]); a3 = fmaf(hh[s+3], Cv[s+3], a3);
        }
        g_y[row*DI + d] = (a0 + a1) + (a2 + a3);
    }
}

// ---------------- gate: y = (y + Dp*x) * silu(z) ----------------
__global__ void gate_kernel(const float* __restrict__ Dp, int layer) {
    int idx = blockIdx.x * blockDim.x + threadIdx.x;
    if (idx >= BATCH*L_SEQ*DI) return;
    int d = idx % DI;
    size_t row = idx / DI;
    float z = g_xz[row*(2*DI) + DI + d];
    float y = g_y[idx] + Dp[layer*DI + d] * g_xs[idx];
    g_y[idx] = y * silu_f(z);
}

// ---------------- final: LN(eps 1e-6) + adaLN modulation + head ----------------
__global__ void final_kernel(const float* __restrict__ lin_w,
                             const float* __restrict__ lin_b,
                             float* __restrict__ out) {
    int row = blockIdx.x;     // b*L + l
    int b = row >> 10;
    int l = row & 1023;
    const float* hrow = g_h + (size_t)row * DM;
    int tid = threadIdx.x;

    float v[3];
    float s = 0.f, ss = 0.f;
#pragma unroll
    for (int j = 0; j < 3; j++) {
        v[j] = hrow[tid + j*256];
        s += v[j];
        ss = fmaf(v[j], v[j], ss);
    }
    __shared__ float sh[2][8];
    for (int o = 16; o > 0; o >>= 1) {
        s  += __shfl_xor_sync(0xffffffffu, s,  o);
        ss += __shfl_xor_sync(0xffffffffu, ss, o);
    }
    if ((tid & 31) == 0) { sh[0][tid >> 5] = s; sh[1][tid >> 5] = ss; }
    __syncthreads();
    if (tid < 32) {
        float a = (tid < 8) ? sh[0][tid] : 0.f;
        float c = (tid < 8) ? sh[1][tid] : 0.f;
        for (int o = 4; o > 0; o >>= 1) {
            a += __shfl_xor_sync(0xffffffffu, a, o);
            c += __shfl_xor_sync(0xffffffffu, c, o);
        }
        if (tid == 0) { sh[0][0] = a; sh[1][0] = c; }
    }
    __syncthreads();
    float mean = sh[0][0] * (1.f / DM);
    float var  = sh[1][0] * (1.f / DM) - mean * mean;
    float rs = rsqrtf(var + 1e-6f);

    float dot[4] = {0.f, 0.f, 0.f, 0.f};
#pragma unroll
    for (int j = 0; j < 3; j++) {
        int m = tid + j*256;
        float hn = (v[j] - mean) * rs * (1.f + g_ada[b*2*DM + DM + m]) + g_ada[b*2*DM + m];
#pragma unroll
        for (int c = 0; c < 4; c++)
            dot[c] = fmaf(hn, lin_w[c*DM + m], dot[c]);
    }
    for (int o = 16; o > 0; o >>= 1)
#pragma unroll
        for (int c = 0; c < 4; c++)
            dot[c] += __shfl_xor_sync(0xffffffffu, dot[c], o);
    __shared__ float shd[4][8];
    if ((tid & 31) == 0)
#pragma unroll
        for (int c = 0; c < 4; c++) shd[c][tid >> 5] = dot[c];
    __syncthreads();
    if (tid == 0) {
#pragma unroll
        for (int c = 0; c < 4; c++) {
            float tsum = 0.f;
#pragma unroll
            for (int w = 0; w < 8; w++) tsum += shd[c][w];
            out[((b*4 + c) << 10) + l] = tsum + lin_b[c];
        }
    }
}

// ---------------- host launcher ----------------
extern "C" void kernel_launch(void* const* d_in, const int* in_sizes, int n_in,
                              void* d_out, int out_size) {
    const float* x         = (const float*)d_in[0];
    const float* t         = (const float*)d_in[1];
    const float* patch_w   = (const float*)d_in[2];
    const float* patch_b   = (const float*)d_in[3];
    const float* pos       = (const float*)d_in[4];
    const float* t_w1      = (const float*)d_in[5];
    const float* t_b1      = (const float*)d_in[6];
    const float* t_w2      = (const float*)d_in[7];
    const float* t_b2      = (const float*)d_in[8];
    const float* norm_w    = (const float*)d_in[9];
    const float* norm_b    = (const float*)d_in[10];
    const float* in_proj_w = (const float*)d_in[11];
    const float* conv_w    = (const float*)d_in[12];
    const float* conv_b    = (const float*)d_in[13];
    const float* x_proj_w  = (const float*)d_in[14];
    const float* dt_w      = (const float*)d_in[15];
    const float* dt_b      = (const float*)d_in[16];
    const float* A_log     = (const float*)d_in[17];
    const float* Dp        = (const float*)d_in[18];
    const float* out_proj_w= (const float*)d_in[19];
    const float* ada_w     = (const float*)d_in[20];
    const float* ada_b     = (const float*)d_in[21];
    const float* lin_w     = (const float*)d_in[22];
    const float* lin_b     = (const float*)d_in[23];
    const int*   orders    = (const int*)d_in[24];
    float* out = (float*)d_out;

    float *p_u, *p_xz, *p_xs, *p_dbl, *p_dt, *p_y, *p_h, *p_ho;
    cudaGetSymbolAddress((void**)&p_u,   g_u);
    cudaGetSymbolAddress((void**)&p_xz,  g_xz);
    cudaGetSymbolAddress((void**)&p_xs,  g_xs);
    cudaGetSymbolAddress((void**)&p_dbl, g_dbl);
    cudaGetSymbolAddress((void**)&p_dt,  g_dt);
    cudaGetSymbolAddress((void**)&p_y,   g_y);
    cudaGetSymbolAddress((void**)&p_h,   g_h);
    cudaGetSymbolAddress((void**)&p_ho,  g_ho);

    const int M = BATCH * L_SEQ;   // 4096

    init_flags_kernel<<<1, 32>>>();
    precompute_A_kernel<<<(DEPTH*DI*DS + 255)/256, 256>>>(A_log);
    patch_kernel<<<(M*DM + 255)/256, 256>>>(x, patch_w, patch_b, pos);
    tmlp1_kernel<<<BATCH, 256>>>(t, t_w1, t_b1);
    tmlp2_kernel<<<BATCH, 256>>>(t_w2, t_b2);
    ada_kernel<<<BATCH, 256>>>(ada_w, ada_b);

    for (int i = 0; i < DEPTH; i++) {
        ln_gather_kernel<<<M, 256>>>(norm_w, norm_b, orders + i*L_SEQ, i);

        // xz = u @ in_proj_w^T : M x 3072, K=768
        gemm_tn_kernel<<<dim3((2*DI)/GBN, M/GBM), 256>>>(
            p_u, DM, in_proj_w + (size_t)i*2*DI*DM, DM,
            p_xz, 2*DI, M, 2*DI, DM, nullptr, 0, nullptr, nullptr);

        conv_silu_kernel<<<(M*DI + 255)/256, 256>>>(conv_w, conv_b, i);

        // dbl = xs @ x_proj_w^T : M x 80, K=1536
        gemm_tn_kernel<<<dim3((80 + GBN - 1)/GBN, M/GBM), 256>>>(
            p_xs, DI, x_proj_w + (size_t)i*80*DI, DI,
            p_dbl, 80, M, 80, DI, nullptr, 0, nullptr, nullptr);

        // dt = softplus(dbl[:, :48] @ dt_w^T + dt_b) : M x 1536, K=48 (lda=80)
        gemm_tn_kernel<<<dim3(DI/GBN, M/GBM), 256>>>(
            p_dbl, 80, dt_w + (size_t)i*DI*DR, DR,
            p_dt, DI, M, DI, DR, dt_b + i*DI, 2, nullptr, nullptr);

        scan_kernel<<<(BATCH*DI + 63)/64, 64>>>(i);
        gate_kernel<<<(M*DI + 255)/256, 256>>>(Dp, i);

        // h[b, order[p]] = ho[b, p] + y @ out_proj_w^T : M x 768, K=1536
        gemm_tn_kernel<<<dim3(DM/GBN, M/GBM), 256>>>(
            p_y, DI, out_proj_w + (size_t)i*DM*DI, DI,
            p_h, DM, M, DM, DI, nullptr, 0, p_ho, orders + i*L_SEQ);
    }

    final_kernel<<<M, 256>>>(lin_w, lin_b, out);
}

// round 3
// speedup vs baseline: 1.4560x; 1.4560x over previous
#include <cuda_runtime.h>
#include <cuda_bf16.h>
#include <cstdint>
#include <math.h>

#define BATCH   4
#define L_SEQ   1024
#define DM      768
#define DI      1536
#define DS      16
#define DR      48
#define DEPTH   4
#define M_ROWS  (BATCH*L_SEQ)

// ---------------- fp32 scratch ----------------
__device__ float g_h  [M_ROWS*DM];
__device__ float g_ho [M_ROWS*DM];
__device__ float g_xz [M_ROWS*2*DI];
__device__ float g_xs [M_ROWS*DI];
__device__ float g_dbl[M_ROWS*80];
__device__ float g_dt [M_ROWS*DI];
__device__ float g_y  [M_ROWS*DI];
__device__ float g_mid[BATCH*DM];
__device__ float g_c  [BATCH*DM];
__device__ float g_ada[BATCH*2*DM];
__device__ float g_A  [DEPTH*DI*DS];
__device__ int   g_pflag[DEPTH];

// ---------------- bf16 split activations ----------------
__device__ __align__(128) __nv_bfloat16 g_u_hi [M_ROWS*DM],  g_u_lo [M_ROWS*DM];
__device__ __align__(128) __nv_bfloat16 g_xs_hi[M_ROWS*DI],  g_xs_lo[M_ROWS*DI];
__device__ __align__(128) __nv_bfloat16 g_y_hi [M_ROWS*DI],  g_y_lo [M_ROWS*DI];
__device__ __align__(128) __nv_bfloat16 g_dp_hi[M_ROWS*64],  g_dp_lo[M_ROWS*64];

// ---------------- bf16 split weights (x_proj padded N 80->128) ----------------
__device__ __align__(128) __nv_bfloat16 g_win_hi [DEPTH*2*DI*DM], g_win_lo [DEPTH*2*DI*DM];
__device__ __align__(128) __nv_bfloat16 g_wout_hi[DEPTH*DM*DI],   g_wout_lo[DEPTH*DM*DI];
__device__ __align__(128) __nv_bfloat16 g_wxp_hi [DEPTH*128*DI],  g_wxp_lo [DEPTH*128*DI];
__device__ __align__(128) __nv_bfloat16 g_wdt_hi [DEPTH*DI*64],   g_wdt_lo [DEPTH*DI*64];

// ---------------- helpers ----------------
__device__ __forceinline__ float silu_f(float v) { return v / (1.f + __expf(-v)); }

__device__ __forceinline__ void split2(float v, __nv_bfloat16& h, __nv_bfloat16& l) {
    h = __float2bfloat16(v);
    l = __float2bfloat16(v - __bfloat162float(h));
}

__device__ __forceinline__ uint32_t smem_u32(const void* p) {
    uint32_t a;
    asm("{ .reg .u64 t; cvta.to.shared.u64 t, %1; cvt.u32.u64 %0, t; }" : "=r"(a) : "l"(p));
    return a;
}

#define CP_ASYNC16(dst, src) asm volatile("cp.async.cg.shared.global [%0], [%1], 16;" :: "r"(dst), "l"(src) : "memory")
#define CP_COMMIT()  asm volatile("cp.async.commit_group;" ::: "memory")
#define CP_WAIT1()   asm volatile("cp.async.wait_group 1;" ::: "memory")
#define CP_WAIT0()   asm volatile("cp.async.wait_group 0;" ::: "memory")

#define LDSM4(r, addr) asm volatile("ldmatrix.sync.aligned.m8n8.x4.shared.b16 {%0,%1,%2,%3}, [%4];" \
    : "=r"((r)[0]),"=r"((r)[1]),"=r"((r)[2]),"=r"((r)[3]) : "r"(addr))
#define LDSM2(r, addr) asm volatile("ldmatrix.sync.aligned.m8n8.x2.shared.b16 {%0,%1}, [%2];" \
    : "=r"((r)[0]),"=r"((r)[1]) : "r"(addr))

#define MMA_BF16(d, a, b) \
    asm volatile("mma.sync.aligned.m16n8k16.row.col.f32.bf16.bf16.f32 " \
        "{%0,%1,%2,%3}, {%4,%5,%6,%7}, {%8,%9}, {%0,%1,%2,%3};" \
        : "+f"((d)[0]),"+f"((d)[1]),"+f"((d)[2]),"+f"((d)[3]) \
        : "r"((a)[0]),"r"((a)[1]),"r"((a)[2]),"r"((a)[3]), "r"((b)[0]),"r"((b)[1]))

// ============================================================
// bf16x3 split GEMM on mma.sync: C(M x N) = A @ W^T, fp32 accum.
// Tiles: CTA 128x128, warp 64x32, K-chunk 32, double-buffered cp.async.
// mode: 0 plain, 1 bias+softplus, 2 residual+row-scatter, 3 fp32+split
// ============================================================
#define KC        32
#define ROWB      80        // smem bytes per row (32 bf16 + 8 pad)
#define SEGB      10240     // 128 rows * 80B
#define STAGEB    40960     // 4 segments (Ahi,Alo,Whi,Wlo)

__global__ void __launch_bounds__(256)
gemm_mma(const __nv_bfloat16* __restrict__ Ahi, const __nv_bfloat16* __restrict__ Alo, int lda,
         const __nv_bfloat16* __restrict__ Whi, const __nv_bfloat16* __restrict__ Wlo, int ldw,
         float* __restrict__ C, int ldc, int kblocks,
         const float* __restrict__ bias, int mode,
         const float* __restrict__ add, const int* __restrict__ scat,
         __nv_bfloat16* __restrict__ shi, __nv_bfloat16* __restrict__ slo) {
    extern __shared__ char smem[];
    const int tid  = threadIdx.x;
    const int m0   = blockIdx.y * 128;
    const int n0   = blockIdx.x * 128;
    const int wid  = tid >> 5, lane = tid & 31;
    const int wm   = wid & 1;          // 2 warps over M (64 rows each)
    const int wn   = wid >> 1;         // 4 warps over N (32 cols each)
    const uint32_t sb = smem_u32(smem);

    auto load_stage = [&](int s, int kb) {
        uint32_t base = sb + (uint32_t)s * STAGEB;
#pragma unroll
        for (int i = 0; i < 8; i++) {
            int u = tid + i * 256;          // 0..2047
            int seg = u >> 9;               // 0:Ahi 1:Alo 2:Whi 3:Wlo
            int v = u & 511;
            int r = v >> 2, c = v & 3;
            const __nv_bfloat16* src;
            if      (seg == 0) src = Ahi + (size_t)(m0 + r) * lda + kb * KC + c * 8;
            else if (seg == 1) src = Alo + (size_t)(m0 + r) * lda + kb * KC + c * 8;
            else if (seg == 2) src = Whi + (size_t)(n0 + r) * ldw + kb * KC + c * 8;
            else               src = Wlo + (size_t)(n0 + r) * ldw + kb * KC + c * 8;
            uint32_t dst = base + (uint32_t)seg * SEGB + (uint32_t)(r * ROWB + c * 16);
            CP_ASYNC16(dst, src);
        }
        CP_COMMIT();
    };

    float acc[4][4][4];
#pragma unroll
    for (int i = 0; i < 4; i++)
#pragma unroll
        for (int j = 0; j < 4; j++)
#pragma unroll
            for (int k = 0; k < 4; k++) acc[i][j][k] = 0.f;

    load_stage(0, 0);

    for (int kb = 0; kb < kblocks; kb++) {
        int cur = kb & 1;
        if (kb + 1 < kblocks) { load_stage(cur ^ 1, kb + 1); CP_WAIT1(); }
        else                  { CP_WAIT0(); }
        __syncthreads();

        uint32_t aHiB = sb + (uint32_t)cur * STAGEB;
        uint32_t aLoB = aHiB + SEGB;
        uint32_t wHiB = aHiB + 2 * SEGB;
        uint32_t wLoB = aHiB + 3 * SEGB;

#pragma unroll
        for (int ks = 0; ks < 2; ks++) {
            uint32_t ah[4][4], al[4][4];
#pragma unroll
            for (int mi = 0; mi < 4; mi++) {
                uint32_t off = (uint32_t)((wm * 64 + mi * 16 + (lane & 15)) * ROWB
                                          + ks * 32 + (lane >> 4) * 16);
                LDSM4(ah[mi], aHiB + off);
                LDSM4(al[mi], aLoB + off);
            }
            uint32_t bh[4][2], bl[4][2];
#pragma unroll
            for (int ni = 0; ni < 4; ni++) {
                uint32_t off = (uint32_t)((wn * 32 + ni * 8 + (lane & 7)) * ROWB
                                          + ks * 32 + ((lane >> 3) & 1) * 16);
                LDSM2(bh[ni], wHiB + off);
                LDSM2(bl[ni], wLoB + off);
            }
#pragma unroll
            for (int mi = 0; mi < 4; mi++)
#pragma unroll
                for (int ni = 0; ni < 4; ni++) {
                    MMA_BF16(acc[mi][ni], ah[mi], bh[ni]);
                    MMA_BF16(acc[mi][ni], ah[mi], bl[ni]);
                    MMA_BF16(acc[mi][ni], al[mi], bh[ni]);
                }
        }
        __syncthreads();
    }

    // ---- epilogue ----
    auto epi = [&](int row, int col, float v) {
        if (mode == 1) {
            v += bias[col];
            v = fmaxf(v, 0.f) + log1pf(__expf(-fabsf(v)));
            C[(size_t)row * ldc + col] = v;
        } else if (mode == 2) {
            v += add[(size_t)row * ldc + col];
            int orow = (row & ~1023) | scat[row & 1023];
            C[(size_t)orow * ldc + col] = v;
        } else if (mode == 3) {
            if (col < 80) C[(size_t)row * 80 + col] = v;
            if (col < 64) {
                __nv_bfloat16 h, l;
                if (col < 48) split2(v, h, l);
                else { h = __float2bfloat16(0.f); l = h; }
                shi[(size_t)row * 64 + col] = h;
                slo[(size_t)row * 64 + col] = l;
            }
        } else {
            C[(size_t)row * ldc + col] = v;
        }
    };

#pragma unroll
    for (int mi = 0; mi < 4; mi++) {
        int rbase = m0 + wm * 64 + mi * 16 + (lane >> 2);
#pragma unroll
        for (int ni = 0; ni < 4; ni++) {
            int cbase = n0 + wn * 32 + ni * 8 + (lane & 3) * 2;
            epi(rbase,     cbase,     acc[mi][ni][0]);
            epi(rbase,     cbase + 1, acc[mi][ni][1]);
            epi(rbase + 8, cbase,     acc[mi][ni][2]);
            epi(rbase + 8, cbase + 1, acc[mi][ni][3]);
        }
    }
}

// ---------------- weight splits ----------------
__global__ void split_kernel(const float* __restrict__ w,
                             __nv_bfloat16* __restrict__ hi,
                             __nv_bfloat16* __restrict__ lo, int n) {
    int i = blockIdx.x * blockDim.x + threadIdx.x;
    if (i >= n) return;
    split2(w[i], hi[i], lo[i]);
}

__global__ void split_dtw_kernel(const float* __restrict__ w) {  // pad K 48 -> 64
    int i = blockIdx.x * blockDim.x + threadIdx.x;
    if (i >= DEPTH * DI * 64) return;
    int k = i & 63;
    int rowg = i >> 6;
    __nv_bfloat16 h, l;
    if (k < 48) split2(w[rowg * 48 + k], h, l);
    else { h = __float2bfloat16(0.f); l = h; }
    g_wdt_hi[i] = h; g_wdt_lo[i] = l;
}

__global__ void split_xpw_kernel(const float* __restrict__ w) { // pad N 80 -> 128
    int i = blockIdx.x * blockDim.x + threadIdx.x;
    if (i >= DEPTH * 128 * DI) return;
    int k = i % DI;
    int n = (i / DI) & 127;
    int layer = i / (128 * DI);
    __nv_bfloat16 h, l;
    if (n < 80) split2(w[(size_t)layer * 80 * DI + (size_t)n * DI + k], h, l);
    else { h = __float2bfloat16(0.f); l = h; }
    g_wxp_hi[i] = h; g_wxp_lo[i] = l;
}

// ---------------- A precompute + pow-trick flag ----------------
__global__ void init_flags_kernel() { if (threadIdx.x < DEPTH) g_pflag[threadIdx.x] = 1; }

__global__ void precompute_A_kernel(const float* __restrict__ A_log) {
    int idx = blockIdx.x * blockDim.x + threadIdx.x;
    if (idx >= DEPTH*DI*DS) return;
    int s = idx % DS;
    int layer = idx / (DI*DS);
    float a = -expf(A_log[idx]);
    g_A[idx] = a;
    if (fabsf(a + (float)(s + 1)) > 2e-6f * (float)(s + 1))
        atomicAnd(&g_pflag[layer], 0);
}

// ---------------- patch embed ----------------
__global__ void patch_kernel(const float* __restrict__ x, const float* __restrict__ pw,
                             const float* __restrict__ pb, const float* __restrict__ pos) {
    int idx = blockIdx.x * blockDim.x + threadIdx.x;
    if (idx >= M_ROWS*DM) return;
    int m = idx % DM;
    int bl = idx / DM;
    int b = bl >> 10, l = bl & 1023;
    float acc = pb[m] + pos[(size_t)l*DM + m];
#pragma unroll
    for (int c = 0; c < 4; c++)
        acc = fmaf(x[((b*4 + c) << 10) + l], pw[m*4 + c], acc);
    g_h[idx] = acc;
}

// ---------------- time MLP (warp-per-output) ----------------
__global__ void tmlp1_kernel(const float* __restrict__ t, const float* __restrict__ w1,
                             const float* __restrict__ b1) {
    int b = blockIdx.y;
    int tid = threadIdx.x, wid = tid >> 5, lane = tid & 31;
    __shared__ float temb[256];
    {
        float tv = t[b];
        int f = tid;
        if (f < 128) temb[f] = cosf(tv * expf(-logf(10000.f) * (float)f / 128.f));
        else         temb[f] = sinf(tv * expf(-logf(10000.f) * (float)(f-128) / 128.f));
    }
    __syncthreads();
    int m = blockIdx.x * 8 + wid;
    const float* w = w1 + (size_t)m * 256;
    float acc = 0.f;
    for (int f = lane; f < 256; f += 32) acc = fmaf(temb[f], w[f], acc);
    for (int o = 16; o > 0; o >>= 1) acc += __shfl_xor_sync(0xffffffffu, acc, o);
    if (lane == 0) { acc += b1[m]; g_mid[b*DM + m] = silu_f(acc); }
}

__global__ void tmlp2_kernel(const float* __restrict__ w2, const float* __restrict__ b2) {
    int b = blockIdx.y;
    int tid = threadIdx.x, wid = tid >> 5, lane = tid & 31;
    __shared__ float mid[DM];
    for (int k = tid; k < DM; k += 256) mid[k] = g_mid[b*DM + k];
    __syncthreads();
    int m = blockIdx.x * 8 + wid;
    const float* w = w2 + (size_t)m * DM;
    float acc = 0.f;
    for (int k = lane; k < DM; k += 32) acc = fmaf(mid[k], w[k], acc);
    for (int o = 16; o > 0; o >>= 1) acc += __shfl_xor_sync(0xffffffffu, acc, o);
    if (lane == 0) g_c[b*DM + m] = acc + b2[m];
}

__global__ void ada_kernel(const float* __restrict__ w, const float* __restrict__ bias) {
    int b = blockIdx.y;
    int tid = threadIdx.x, wid = tid >> 5, lane = tid & 31;
    __shared__ float sc[DM];
    for (int k = tid; k < DM; k += 256) sc[k] = silu_f(g_c[b*DM + k]);
    __syncthreads();
    int n = blockIdx.x * 8 + wid;
    const float* wr = w + (size_t)n * DM;
    float acc = 0.f;
    for (int k = lane; k < DM; k += 32) acc = fmaf(sc[k], wr[k], acc);
    for (int o = 16; o > 0; o >>= 1) acc += __shfl_xor_sync(0xffffffffu, acc, o);
    if (lane == 0) g_ada[b*2*DM + n] = acc + bias[n];
}

// ---------------- gather + LayerNorm (writes ho fp32, u split) ----------------
__global__ void ln_gather_kernel(const float* __restrict__ norm_w,
                                 const float* __restrict__ norm_b,
                                 const int* __restrict__ order, int layer) {
    int row = blockIdx.x;
    int p = row & 1023, b = row >> 10;
    int src = order[p];
    const float* hrow = g_h + (size_t)(b*L_SEQ + src) * DM;
    float* horow = g_ho + (size_t)row * DM;
    int tid = threadIdx.x;

    float v[3];
    float s = 0.f, ss = 0.f;
#pragma unroll
    for (int j = 0; j < 3; j++) {
        v[j] = hrow[tid + j*256];
        s += v[j];
        ss = fmaf(v[j], v[j], ss);
    }
    __shared__ float sh[2][8];
    for (int o = 16; o > 0; o >>= 1) {
        s  += __shfl_xor_sync(0xffffffffu, s,  o);
        ss += __shfl_xor_sync(0xffffffffu, ss, o);
    }
    if ((tid & 31) == 0) { sh[0][tid >> 5] = s; sh[1][tid >> 5] = ss; }
    __syncthreads();
    if (tid < 32) {
        float a = (tid < 8) ? sh[0][tid] : 0.f;
        float c = (tid < 8) ? sh[1][tid] : 0.f;
        for (int o = 4; o > 0; o >>= 1) {
            a += __shfl_xor_sync(0xffffffffu, a, o);
            c += __shfl_xor_sync(0xffffffffu, c, o);
        }
        if (tid == 0) { sh[0][0] = a; sh[1][0] = c; }
    }
    __syncthreads();
    float mean = sh[0][0] * (1.f / DM);
    float var  = sh[1][0] * (1.f / DM) - mean * mean;
    float rs = rsqrtf(var + 1e-5f);
#pragma unroll
    for (int j = 0; j < 3; j++) {
        int m = tid + j*256;
        horow[m] = v[j];
        float u = (v[j] - mean) * rs * norm_w[layer*DM + m] + norm_b[layer*DM + m];
        split2(u, g_u_hi[(size_t)row*DM + m], g_u_lo[(size_t)row*DM + m]);
    }
}

// ---------------- causal depthwise conv (k=4) + SiLU + split ----------------
__global__ void conv_silu_kernel(const float* __restrict__ conv_w,
                                 const float* __restrict__ conv_b, int layer) {
    int idx = blockIdx.x * blockDim.x + threadIdx.x;
    if (idx >= M_ROWS*DI) return;
    int d = idx % DI;
    int row = idx / DI;
    int p = row & 1023;
    float acc = conv_b[layer*DI + d];
    const float* w = conv_w + ((size_t)(layer*DI + d)) * 4;
#pragma unroll
    for (int k = 0; k < 4; k++) {
        int pp = p - 3 + k;
        if (pp >= 0)
            acc = fmaf(w[k], g_xz[((size_t)(row - 3 + k)) * (2*DI) + d], acc);
    }
    float v = silu_f(acc);
    g_xs[(size_t)row*DI + d] = v;
    split2(v, g_xs_hi[idx], g_xs_lo[idx]);
}

// ---------------- selective scan ----------------
__global__ void scan_kernel(int layer) {
    int t = blockIdx.x * blockDim.x + threadIdx.x;
    if (t >= BATCH*DI) return;
    int b = t / DI, d = t % DI;
    int flag = g_pflag[layer];
    const float* arow = g_A + (size_t)(layer*DI + d) * DS;

    float hh[16];
#pragma unroll
    for (int s = 0; s < 16; s++) hh[s] = 0.f;

    size_t base = (size_t)b * L_SEQ;
    for (int p = 0; p < L_SEQ; p++) {
        size_t row = base + p;
        float dtv = g_dt[row*DI + d];
        float xv  = g_xs[row*DI + d];
        float dtx = dtv * xv;

        const float4* Bp = (const float4*)(g_dbl + row*80 + 48);
        const float4* Cp = (const float4*)(g_dbl + row*80 + 64);
        float Bv[16], Cv[16];
#pragma unroll
        for (int q = 0; q < 4; q++) {
            float4 fb = Bp[q];
            Bv[4*q+0]=fb.x; Bv[4*q+1]=fb.y; Bv[4*q+2]=fb.z; Bv[4*q+3]=fb.w;
            float4 fc = Cp[q];
            Cv[4*q+0]=fc.x; Cv[4*q+1]=fc.y; Cv[4*q+2]=fc.z; Cv[4*q+3]=fc.w;
        }

        float tm[16];
        if (flag) {
            float e1 = __expf(-dtv);
            float e2 = e1*e1, e4 = e2*e2, e8 = e4*e4;
            tm[0]=e1;       tm[1]=e2;       tm[2]=e2*e1;     tm[3]=e4;
            tm[4]=e4*e1;    tm[5]=e4*e2;    tm[6]=e4*tm[2];  tm[7]=e8;
            tm[8]=e8*e1;    tm[9]=e8*e2;    tm[10]=e8*tm[2]; tm[11]=e8*e4;
            tm[12]=e8*tm[4];tm[13]=e8*tm[5];tm[14]=e8*tm[6]; tm[15]=e8*e8;
        } else {
#pragma unroll
            for (int s = 0; s < 16; s++) tm[s] = __expf(dtv * arow[s]);
        }

        float a0=0.f, a1=0.f, a2=0.f, a3=0.f;
#pragma unroll
        for (int s = 0; s < 16; s += 4) {
            hh[s+0] = fmaf(hh[s+0], tm[s+0], dtx * Bv[s+0]); a0 = fmaf(hh[s+0], Cv[s+0], a0);
            hh[s+1] = fmaf(hh[s+1], tm[s+1], dtx * Bv[s+1]); a1 = fmaf(hh[s+1], Cv[s+1], a1);
            hh[s+2] = fmaf(hh[s+2], tm[s+2], dtx * Bv[s+2]); a2 = fmaf(hh[s+2], Cv[s+2], a2);
            hh[s+3] = fmaf(hh[s+3], tm[s+3], dtx * Bv[s+3]); a3 = fmaf(hh[s+3], Cv[s+3], a3);
        }
        g_y[row*DI + d] = (a0 + a1) + (a2 + a3);
    }
}

// ---------------- gate: y = (y + Dp*x)*silu(z)  -> split ----------------
__global__ void gate_kernel(const float* __restrict__ Dp, int layer) {
    int idx = blockIdx.x * blockDim.x + threadIdx.x;
    if (idx >= M_ROWS*DI) return;
    int d = idx % DI;
    size_t row = idx / DI;
    float z = g_xz[row*(2*DI) + DI + d];
    float y = g_y[idx] + Dp[layer*DI + d] * g_xs[idx];
    y *= silu_f(z);
    split2(y, g_y_hi[idx], g_y_lo[idx]);
}

// ---------------- final LN + adaLN + head ----------------
__global__ void final_kernel(const float* __restrict__ lin_w,
                             const float* __restrict__ lin_b,
                             float* __restrict__ out) {
    int row = blockIdx.x;
    int b = row >> 10, l = row & 1023;
    const float* hrow = g_h + (size_t)row * DM;
    int tid = threadIdx.x;

    float v[3];
    float s = 0.f, ss = 0.f;
#pragma unroll
    for (int j = 0; j < 3; j++) {
        v[j] = hrow[tid + j*256];
        s += v[j];
        ss = fmaf(v[j], v[j], ss);
    }
    __shared__ float sh[2][8];
    for (int o = 16; o > 0; o >>= 1) {
        s  += __shfl_xor_sync(0xffffffffu, s,  o);
        ss += __shfl_xor_sync(0xffffffffu, ss, o);
    }
    if ((tid & 31) == 0) { sh[0][tid >> 5] = s; sh[1][tid >> 5] = ss; }
    __syncthreads();
    if (tid < 32) {
        float a = (tid < 8) ? sh[0][tid] : 0.f;
        float c = (tid < 8) ? sh[1][tid] : 0.f;
        for (int o = 4; o > 0; o >>= 1) {
            a += __shfl_xor_sync(0xffffffffu, a, o);
            c += __shfl_xor_sync(0xffffffffu, c, o);
        }
        if (tid == 0) { sh[0][0] = a; sh[1][0] = c; }
    }
    __syncthreads();
    float mean = sh[0][0] * (1.f / DM);
    float var  = sh[1][0] * (1.f / DM) - mean * mean;
    float rs = rsqrtf(var + 1e-6f);

    float dot[4] = {0.f, 0.f, 0.f, 0.f};
#pragma unroll
    for (int j = 0; j < 3; j++) {
        int m = tid + j*256;
        float hn = (v[j] - mean) * rs * (1.f + g_ada[b*2*DM + DM + m]) + g_ada[b*2*DM + m];
#pragma unroll
        for (int c = 0; c < 4; c++)
            dot[c] = fmaf(hn, lin_w[c*DM + m], dot[c]);
    }
    for (int o = 16; o > 0; o >>= 1)
#pragma unroll
        for (int c = 0; c < 4; c++)
            dot[c] += __shfl_xor_sync(0xffffffffu, dot[c], o);
    __shared__ float shd[4][8];
    if ((tid & 31) == 0)
#pragma unroll
        for (int c = 0; c < 4; c++) shd[c][tid >> 5] = dot[c];
    __syncthreads();
    if (tid == 0) {
#pragma unroll
        for (int c = 0; c < 4; c++) {
            float tsum = 0.f;
#pragma unroll
            for (int w = 0; w < 8; w++) tsum += shd[c][w];
            out[((b*4 + c) << 10) + l] = tsum + lin_b[c];
        }
    }
}

// ---------------- host launcher ----------------
extern "C" void kernel_launch(void* const* d_in, const int* in_sizes, int n_in,
                              void* d_out, int out_size) {
    const float* x         = (const float*)d_in[0];
    const float* t         = (const float*)d_in[1];
    const float* patch_w   = (const float*)d_in[2];
    const float* patch_b   = (const float*)d_in[3];
    const float* pos       = (const float*)d_in[4];
    const float* t_w1      = (const float*)d_in[5];
    const float* t_b1      = (const float*)d_in[6];
    const float* t_w2      = (const float*)d_in[7];
    const float* t_b2      = (const float*)d_in[8];
    const float* norm_w    = (const float*)d_in[9];
    const float* norm_b    = (const float*)d_in[10];
    const float* in_proj_w = (const float*)d_in[11];
    const float* conv_w    = (const float*)d_in[12];
    const float* conv_b    = (const float*)d_in[13];
    const float* x_proj_w  = (const float*)d_in[14];
    const float* dt_w      = (const float*)d_in[15];
    const float* dt_b      = (const float*)d_in[16];
    const float* A_log     = (const float*)d_in[17];
    const float* Dp        = (const float*)d_in[18];
    const float* out_proj_w= (const float*)d_in[19];
    const float* ada_w     = (const float*)d_in[20];
    const float* ada_b     = (const float*)d_in[21];
    const float* lin_w     = (const float*)d_in[22];
    const float* lin_b     = (const float*)d_in[23];
    const int*   orders    = (const int*)d_in[24];
    float* out = (float*)d_out;

    static bool attr_done = false;
    if (!attr_done) {
        cudaFuncSetAttribute(gemm_mma, cudaFuncAttributeMaxDynamicSharedMemorySize, 2*STAGEB);
        attr_done = true;
    }

    float *p_xz, *p_dbl, *p_dt, *p_h, *p_ho;
    cudaGetSymbolAddress((void**)&p_xz,  g_xz);
    cudaGetSymbolAddress((void**)&p_dbl, g_dbl);
    cudaGetSymbolAddress((void**)&p_dt,  g_dt);
    cudaGetSymbolAddress((void**)&p_h,   g_h);
    cudaGetSymbolAddress((void**)&p_ho,  g_ho);
    __nv_bfloat16 *p_uh, *p_ul, *p_xsh, *p_xsl, *p_yh, *p_yl, *p_dph, *p_dpl;
    __nv_bfloat16 *p_wih, *p_wil, *p_woh, *p_wol, *p_wxh, *p_wxl, *p_wdh, *p_wdl;
    cudaGetSymbolAddress((void**)&p_uh,  g_u_hi);  cudaGetSymbolAddress((void**)&p_ul,  g_u_lo);
    cudaGetSymbolAddress((void**)&p_xsh, g_xs_hi); cudaGetSymbolAddress((void**)&p_xsl, g_xs_lo);
    cudaGetSymbolAddress((void**)&p_yh,  g_y_hi);  cudaGetSymbolAddress((void**)&p_yl,  g_y_lo);
    cudaGetSymbolAddress((void**)&p_dph, g_dp_hi); cudaGetSymbolAddress((void**)&p_dpl, g_dp_lo);
    cudaGetSymbolAddress((void**)&p_wih, g_win_hi);  cudaGetSymbolAddress((void**)&p_wil, g_win_lo);
    cudaGetSymbolAddress((void**)&p_woh, g_wout_hi); cudaGetSymbolAddress((void**)&p_wol, g_wout_lo);
    cudaGetSymbolAddress((void**)&p_wxh, g_wxp_hi);  cudaGetSymbolAddress((void**)&p_wxl, g_wxp_lo);
    cudaGetSymbolAddress((void**)&p_wdh, g_wdt_hi);  cudaGetSymbolAddress((void**)&p_wdl, g_wdt_lo);

    const int M = M_ROWS;  // 4096

    init_flags_kernel<<<1, 32>>>();
    precompute_A_kernel<<<(DEPTH*DI*DS + 255)/256, 256>>>(A_log);
    split_kernel<<<(DEPTH*2*DI*DM + 255)/256, 256>>>(in_proj_w,  p_wih, p_wil, DEPTH*2*DI*DM);
    split_kernel<<<(DEPTH*DM*DI + 255)/256, 256>>>(out_proj_w, p_woh, p_wol, DEPTH*DM*DI);
    split_xpw_kernel<<<(DEPTH*128*DI + 255)/256, 256>>>(x_proj_w);
    split_dtw_kernel<<<(DEPTH*DI*64 + 255)/256, 256>>>(dt_w);

    patch_kernel<<<(M*DM + 255)/256, 256>>>(x, patch_w, patch_b, pos);
    tmlp1_kernel<<<dim3(DM/8, BATCH), 256>>>(t, t_w1, t_b1);
    tmlp2_kernel<<<dim3(DM/8, BATCH), 256>>>(t_w2, t_b2);
    ada_kernel<<<dim3(2*DM/8, BATCH), 256>>>(ada_w, ada_b);

    for (int i = 0; i < DEPTH; i++) {
        ln_gather_kernel<<<M, 256>>>(norm_w, norm_b, orders + i*L_SEQ, i);

        // xz = u @ in_proj_w^T : (4096 x 3072), K=768
        gemm_mma<<<dim3(2*DI/128, M/128), 256, 2*STAGEB>>>(
            p_uh, p_ul, DM, p_wih + (size_t)i*2*DI*DM, p_wil + (size_t)i*2*DI*DM, DM,
            p_xz, 2*DI, DM/KC, nullptr, 0, nullptr, nullptr, nullptr, nullptr);

        conv_silu_kernel<<<(M*DI + 255)/256, 256>>>(conv_w, conv_b, i);

        // dbl = xs @ x_proj_w^T : (4096 x 80 padded to 128), K=1536 ; fp32 + split
        gemm_mma<<<dim3(1, M/128), 256, 2*STAGEB>>>(
            p_xsh, p_xsl, DI, p_wxh + (size_t)i*128*DI, p_wxl + (size_t)i*128*DI, DI,
            p_dbl, 80, DI/KC, nullptr, 3, nullptr, nullptr, p_dph, p_dpl);

        // dt = softplus(dbl[:,:48] @ dt_w^T + dt_b) : (4096 x 1536), K=64 padded
        gemm_mma<<<dim3(DI/128, M/128), 256, 2*STAGEB>>>(
            p_dph, p_dpl, 64, p_wdh + (size_t)i*DI*64, p_wdl + (size_t)i*DI*64, 64,
            p_dt, DI, 64/KC, dt_b + i*DI, 1, nullptr, nullptr, nullptr, nullptr);

        scan_kernel<<<(BATCH*DI + 127)/128, 128>>>(i);
        gate_kernel<<<(M*DI + 255)/256, 256>>>(Dp, i);

        // h[b, order[p]] = ho[b,p] + y @ out_proj_w^T : (4096 x 768), K=1536
        gemm_mma<<<dim3(DM/128, M/128), 256, 2*STAGEB>>>(
            p_yh, p_yl, DI, p_woh + (size_t)i*DM*DI, p_wol + (size_t)i*DM*DI, DI,
            p_h, DM, DI/KC, nullptr, 2, p_ho, orders + i*L_SEQ, nullptr, nullptr);
    }

    final_kernel<<<M, 256>>>(lin_w, lin_b, out);
}